// round 10
// baseline (speedup 1.0000x reference)
#include <cuda_runtime.h>
#include <cstdint>
#include <cstddef>

#define B_N    16
#define C_IN   256
#define C_OUT  128
#define H_IN   64
#define W_IN   64
#define H_OUT  128
#define W_OUT  128

// Synthesized per-sample weights in MMA-FRAGMENT-MAJOR layout, tf32-pre-rounded:
//   u32 index = ((((b*4+cls)*64 + kc)*2 + kstep)*8 + cotile)*128 + lane*4 + reg
// where k = ci*4+tap: kc=k>>4, kstep=(k>>3)&1, t=k&3, hk=(k>>2)&1,
//       co: cotile=co>>4, g=co&7, hc=(co>>3)&1, lane=g*4+t, reg=hc+2*hk.
// 32 MiB.
__device__ __align__(16) float g_wsyn[(size_t)B_N * 4 * 1024 * 128];

// ===========================================================================
// Helpers
// ===========================================================================
__device__ __forceinline__ uint32_t to_tf32(float f) {
    uint32_t r;
    asm("cvt.rna.tf32.f32 %0, %1;" : "=r"(r) : "f"(f));
    return r;
}
// m16n8k8 tf32 MMA (sm_80 baseline feature — valid on generic sm_103 target)
__device__ __forceinline__ void mma8(float* d,
                                     uint32_t a0, uint32_t a1, uint32_t a2, uint32_t a3,
                                     uint32_t b0, uint32_t b1) {
    asm volatile(
        "mma.sync.aligned.m16n8k8.row.col.f32.tf32.tf32.f32 "
        "{%0,%1,%2,%3}, {%4,%5,%6,%7}, {%8,%9}, {%0,%1,%2,%3};"
        : "+f"(d[0]), "+f"(d[1]), "+f"(d[2]), "+f"(d[3])
        : "r"(a0), "r"(a1), "r"(a2), "r"(a3), "r"(b0), "r"(b1));
}

// ===========================================================================
// Kernel 1: weight synthesis directly into fragment-major layout.
// Grid: 128 blocks = (kc 0..63, kstep 0..1). 256 threads = (cotile 8, lane 32).
// Each thread produces the 4 fragment regs (hc,hk combos) for its (g,t) slot,
// for all 16 samples x 4 classes -> 64 perfectly-coalesced STG.128.
// Each weight element is read exactly once.
// ===========================================================================
__global__ __launch_bounds__(256)
void synth_kernel(
    const float* __restrict__ feature, const float* __restrict__ weight,
    const float* __restrict__ tb,  const float* __restrict__ tq,
    const float* __restrict__ tn,  const float* __restrict__ tqx,
    const float* __restrict__ mb,  const float* __restrict__ mq,
    const float* __restrict__ mn,  const float* __restrict__ mqx)
{
    __shared__ float sf[64];
    const int tid = threadIdx.x;
    const int blk = blockIdx.x;           // 0..127
    const int kc = blk >> 1, kstep = blk & 1;
    const int cotile = tid >> 5;
    const int lane = tid & 31;
    const int g = lane >> 2, t = lane & 3;

    if (tid < 64) sf[tid] = feature[tid];
    __syncthreads();

    const int ci0 = kc * 4 + kstep * 2;   // reg hk: ci = ci0 + hk
    const int co0 = cotile * 16 + g;      // reg hc: co = co0 + 8*hc
    const int dy = t >> 1, dx = t & 1;    // tap = t

    // m values (independent of cls)
    float mv[4][4];   // [j][r], r = hc + 2*hk
#pragma unroll
    for (int r = 0; r < 4; r++) {
        int ci = ci0 + (r >> 1);
        int co = co0 + (r & 1) * 8;
        int mi = ci * C_OUT + co;
        mv[0][r] = __ldg(mb  + mi);
        mv[1][r] = __ldg(mq  + mi);
        mv[2][r] = __ldg(mn  + mi);
        mv[3][r] = __ldg(mqx + mi);
    }

    uint32_t* __restrict__ wout = (uint32_t*)g_wsyn;

#pragma unroll
    for (int cls = 0; cls < 4; cls++) {
        int kh = (cls & 2) ? (2 - 2 * dy) : (1 + 2 * dy);
        int kw = (cls & 1) ? (2 - 2 * dx) : (1 + 2 * dx);
        float wv[4], pv[4][4];
#pragma unroll
        for (int r = 0; r < 4; r++) {
            int ci = ci0 + (r >> 1);
            int co = co0 + (r & 1) * 8;
            int src = ((ci * C_OUT + co) * 4 + kh) * 4 + kw;
            wv[r]    = __ldg(weight + src);
            pv[0][r] = mv[0][r] * __ldg(tb  + src);
            pv[1][r] = mv[1][r] * __ldg(tq  + src);
            pv[2][r] = mv[2][r] * __ldg(tn  + src);
            pv[3][r] = mv[3][r] * __ldg(tqx + src);
        }
#pragma unroll 4
        for (int b = 0; b < 16; b++) {
            float f0 = sf[b * 4 + 0], f1 = sf[b * 4 + 1];
            float f2 = sf[b * 4 + 2], f3 = sf[b * 4 + 3];
            uint4 u;
            u.x = to_tf32(wv[0] + f0 * pv[0][0] + f1 * pv[1][0] + f2 * pv[2][0] + f3 * pv[3][0]);
            u.y = to_tf32(wv[1] + f0 * pv[0][1] + f1 * pv[1][1] + f2 * pv[2][1] + f3 * pv[3][1]);
            u.z = to_tf32(wv[2] + f0 * pv[0][2] + f1 * pv[1][2] + f2 * pv[2][2] + f3 * pv[3][2]);
            u.w = to_tf32(wv[3] + f0 * pv[0][3] + f1 * pv[1][3] + f2 * pv[2][3] + f3 * pv[3][3]);
            size_t idx = (((((size_t)(b * 4 + cls) * 64 + kc) * 2 + kstep) * 8 + cotile) * 32
                          + lane) * 4;
            *(uint4*)(wout + idx) = u;
        }
    }
}

// ===========================================================================
// Kernel 2: tf32 mma.sync implicit-GEMM deconv.
// Per CTA: (b, cls, ntile): D[co=128, n=128] = sum_k A[k,co]*X[k,n], K=1024.
// 128 threads = 4 warps (2m x 2n), warp tile 64co x 64n.
// A: direct LDG.128 fragments from fragment-major g_wsyn (no smem),
//    register double-buffered per k8 step.
// B: smem double-buffered, chunk K=16, stride 136 (conflict-free frag LDS).
// ===========================================================================
#define SDB 136

__global__ __launch_bounds__(128, 2)
void deconv_mma(const float* __restrict__ x,
                const float* __restrict__ bias,
                const float* __restrict__ prelu_a,
                float* __restrict__ out)
{
    __shared__ uint32_t Bs[2][16 * SDB];

    const int tid  = threadIdx.x;
    const int wid  = tid >> 5;
    const int lane = tid & 31;
    const int g    = lane >> 2;
    const int t    = lane & 3;
    const int warp_m = wid >> 1;         // 0..1
    const int warp_n = wid & 1;          // 0..1
    const int cow = warp_m * 64;
    const int cnw = warp_n * 64;

    const int y0  = blockIdx.x * 2;      // two class-rows (128 n) per CTA
    const int cls = blockIdx.y;
    const int b   = blockIdx.z;
    const int py  = cls >> 1, px = cls & 1;
    const int sy  = py ? 1 : -1;
    const int sx  = px ? 1 : -1;

    // ---- B staging geometry: one thread per n column ----
    const int n  = tid;                  // 0..127
    const int ry = n >> 6, xx = n & 63;
    const int iy1 = y0 + ry + sy;
    const int ix1 = xx + sx;
    const bool oky = (unsigned)iy1 < (unsigned)H_IN;
    const bool okx = (unsigned)ix1 < (unsigned)W_IN;
    const int off0 = (y0 + ry) * W_IN + xx;
    const int dyo  = sy * W_IN;

    const float* __restrict__ xb = x + (size_t)b * (C_IN * H_IN * W_IN);
    // A fragment base (uint4 units): per (b,cls) slice is 32768 uint4.
    const uint4* __restrict__ pa =
        (const uint4*)g_wsyn + (size_t)(b * 4 + cls) * 32768 + warp_m * (4 * 32) + lane;

    float acc[4][8][4];
#pragma unroll
    for (int i = 0; i < 4; i++)
#pragma unroll
        for (int j = 0; j < 8; j++)
#pragma unroll
            for (int q = 0; q < 4; q++) acc[i][j][q] = 0.0f;

    float4 vb[4];
    uint4 afA[4], afB[4];

    auto ldA = [&](int kc, int kstep, uint4* af) {
        const uint4* p = pa + (size_t)(kc * 2 + kstep) * 256;
        af[0] = p[0];
        af[1] = p[32];
        af[2] = p[64];
        af[3] = p[96];
    };
    auto ldB = [&](int kc) {
#pragma unroll
        for (int c = 0; c < 4; c++) {
            const float* xc = xb + (size_t)(kc * 4 + c) * (H_IN * W_IN);
            float4 v;
            v.x = xc[off0];
            v.y = okx ? xc[off0 + sx] : 0.0f;
            v.z = oky ? xc[off0 + dyo] : 0.0f;
            v.w = (oky && okx) ? xc[off0 + dyo + sx] : 0.0f;
            vb[c] = v;
        }
    };
    auto stB = [&](int buf) {
        uint32_t* Bp = Bs[buf];
#pragma unroll
        for (int c = 0; c < 4; c++) {
            Bp[(c * 4 + 0) * SDB + n] = to_tf32(vb[c].x);
            Bp[(c * 4 + 1) * SDB + n] = to_tf32(vb[c].y);
            Bp[(c * 4 + 2) * SDB + n] = to_tf32(vb[c].z);
            Bp[(c * 4 + 3) * SDB + n] = to_tf32(vb[c].w);
        }
    };
    auto compute = [&](int buf, int ks, uint4* af) {
        const uint32_t* Bp = Bs[buf];
        uint32_t bf[8][2];
#pragma unroll
        for (int nt = 0; nt < 8; nt++) {
            int nn = cnw + nt * 8 + g;
            bf[nt][0] = Bp[(ks + t) * SDB + nn];
            bf[nt][1] = Bp[(ks + t + 4) * SDB + nn];
        }
#pragma unroll
        for (int mt = 0; mt < 4; mt++)
#pragma unroll
            for (int nt = 0; nt < 8; nt++)
                mma8(acc[mt][nt], af[mt].x, af[mt].y, af[mt].z, af[mt].w,
                     bf[nt][0], bf[nt][1]);
    };

    // ---- Mainloop: 64 chunks of K=16 ----
    ldB(0);
    stB(0);
    ldA(0, 0, afA);
    __syncthreads();
#pragma unroll 1
    for (int kc = 0; kc < 64; kc++) {
        const int buf = kc & 1;
        if (kc < 63) ldB(kc + 1);          // prefetch next chunk's X gathers
        ldA(kc, 1, afB);                    // prefetch kstep 1 fragments
        compute(buf, 0, afA);
        if (kc < 63) ldA(kc + 1, 0, afA);  // prefetch next chunk kstep 0
        compute(buf, 8, afB);
        if (kc < 63) {
            stB(buf ^ 1);
            __syncthreads();
        }
    }

    // ---- Epilogue: bias + PReLU, interleaved store ----
    const float pa_ = prelu_a[0];
#pragma unroll
    for (int mt = 0; mt < 4; mt++) {
        int c0r = cow + mt * 16 + g;
        float bv0 = __ldg(bias + c0r);
        float bv1 = __ldg(bias + c0r + 8);
#pragma unroll
        for (int rr = 0; rr < 2; rr++) {
            int co = c0r + rr * 8;
            float bi = rr ? bv1 : bv0;
            float* ob = out + (size_t)(b * C_OUT + co) * (H_OUT * W_OUT);
#pragma unroll
            for (int nt = 0; nt < 8; nt++) {
                int n0 = cnw + nt * 8 + t * 2;
                int ry2 = n0 >> 6, xx2 = n0 & 63;
                int oy = (y0 + ry2) * 2 + py;
                int ox = xx2 * 2 + px;
                float v0 = acc[mt][nt][rr * 2 + 0] + bi;
                float v1 = acc[mt][nt][rr * 2 + 1] + bi;
                v0 = (v0 >= 0.0f) ? v0 : pa_ * v0;
                v1 = (v1 >= 0.0f) ? v1 : pa_ * v1;
                ob[oy * W_OUT + ox]     = v0;
                ob[oy * W_OUT + ox + 2] = v1;
            }
        }
    }
}

// ===========================================================================
// Launch. Inputs: x, feature, weight, t_bayer, t_quad, t_nano, t_qxq,
// m_bayer, m_quad, m_nano, m_qxq, bias, prelu_a
// ===========================================================================
extern "C" void kernel_launch(void* const* d_in, const int* in_sizes, int n_in,
                              void* d_out, int out_size)
{
    const float* x       = (const float*)d_in[0];
    const float* feature = (const float*)d_in[1];
    const float* weight  = (const float*)d_in[2];
    const float* tb      = (const float*)d_in[3];
    const float* tq      = (const float*)d_in[4];
    const float* tn      = (const float*)d_in[5];
    const float* tqx     = (const float*)d_in[6];
    const float* mb      = (const float*)d_in[7];
    const float* mq      = (const float*)d_in[8];
    const float* mn      = (const float*)d_in[9];
    const float* mqx     = (const float*)d_in[10];
    const float* bias    = (const float*)d_in[11];
    const float* pa      = (const float*)d_in[12];
    float* out = (float*)d_out;

    // Kernel 1: fragment-major weight synthesis (each src element read once)
    synth_kernel<<<128, 256>>>(feature, weight, tb, tq, tn, tqx, mb, mq, mn, mqx);

    // Kernel 2: 32 n-tiles x 4 parity classes x 16 samples
    dim3 grid(32, 4, 16);
    deconv_mma<<<grid, 128>>>(x, bias, pa, out);
}

// round 11
// speedup vs baseline: 1.0168x; 1.0168x over previous
#include <cuda_runtime.h>
#include <cstdint>
#include <cstddef>

#define B_N    16
#define C_IN   256
#define C_OUT  128
#define H_IN   64
#define W_IN   64
#define H_OUT  128
#define W_OUT  128

// Synthesized per-sample weights in MMA-FRAGMENT-MAJOR layout, tf32-pre-rounded:
//   u32 index = ((((b*4+cls)*64 + kc)*2 + kstep)*8 + cotile)*128 + lane*4 + reg
// where k = ci*4+tap: kc=k>>4, kstep=(k>>3)&1, t=k&3, hk=(k>>2)&1,
//       co: cotile=co>>4, g=co&7, hc=(co>>3)&1, lane=g*4+t, reg=hc+2*hk.
// 32 MiB.
__device__ __align__(16) float g_wsyn[(size_t)B_N * 4 * 1024 * 128];

// ===========================================================================
// Helpers
// ===========================================================================
__device__ __forceinline__ uint32_t to_tf32(float f) {
    uint32_t r;
    asm("cvt.rna.tf32.f32 %0, %1;" : "=r"(r) : "f"(f));
    return r;
}
// m16n8k8 tf32 MMA (sm_80 baseline feature — valid on generic sm_103 target)
__device__ __forceinline__ void mma8(float* d,
                                     uint32_t a0, uint32_t a1, uint32_t a2, uint32_t a3,
                                     uint32_t b0, uint32_t b1) {
    asm volatile(
        "mma.sync.aligned.m16n8k8.row.col.f32.tf32.tf32.f32 "
        "{%0,%1,%2,%3}, {%4,%5,%6,%7}, {%8,%9}, {%0,%1,%2,%3};"
        : "+f"(d[0]), "+f"(d[1]), "+f"(d[2]), "+f"(d[3])
        : "r"(a0), "r"(a1), "r"(a2), "r"(a3), "r"(b0), "r"(b1));
}

// ===========================================================================
// Kernel 1: weight synthesis directly into fragment-major layout.
// Grid: 128 blocks = (kc 0..63, kstep 0..1). 256 threads = (cotile 8, lane 32).
// Each thread produces the 4 fragment regs (hc,hk combos) for its (g,t) slot,
// for all 16 samples x 4 classes -> 64 perfectly-coalesced STG.128.
// Each weight element is read exactly once.
// ===========================================================================
__global__ __launch_bounds__(256)
void synth_kernel(
    const float* __restrict__ feature, const float* __restrict__ weight,
    const float* __restrict__ tb,  const float* __restrict__ tq,
    const float* __restrict__ tn,  const float* __restrict__ tqx,
    const float* __restrict__ mb,  const float* __restrict__ mq,
    const float* __restrict__ mn,  const float* __restrict__ mqx)
{
    __shared__ float sf[64];
    const int tid = threadIdx.x;
    const int blk = blockIdx.x;           // 0..127
    const int kc = blk >> 1, kstep = blk & 1;
    const int cotile = tid >> 5;
    const int lane = tid & 31;
    const int g = lane >> 2, t = lane & 3;

    if (tid < 64) sf[tid] = feature[tid];
    __syncthreads();

    const int ci0 = kc * 4 + kstep * 2;   // reg hk: ci = ci0 + hk
    const int co0 = cotile * 16 + g;      // reg hc: co = co0 + 8*hc
    const int dy = t >> 1, dx = t & 1;    // tap = t

    // m values (independent of cls)
    float mv[4][4];   // [j][r], r = hc + 2*hk
#pragma unroll
    for (int r = 0; r < 4; r++) {
        int ci = ci0 + (r >> 1);
        int co = co0 + (r & 1) * 8;
        int mi = ci * C_OUT + co;
        mv[0][r] = __ldg(mb  + mi);
        mv[1][r] = __ldg(mq  + mi);
        mv[2][r] = __ldg(mn  + mi);
        mv[3][r] = __ldg(mqx + mi);
    }

    uint32_t* __restrict__ wout = (uint32_t*)g_wsyn;

#pragma unroll
    for (int cls = 0; cls < 4; cls++) {
        int kh = (cls & 2) ? (2 - 2 * dy) : (1 + 2 * dy);
        int kw = (cls & 1) ? (2 - 2 * dx) : (1 + 2 * dx);
        float wv[4], pv[4][4];
#pragma unroll
        for (int r = 0; r < 4; r++) {
            int ci = ci0 + (r >> 1);
            int co = co0 + (r & 1) * 8;
            int src = ((ci * C_OUT + co) * 4 + kh) * 4 + kw;
            wv[r]    = __ldg(weight + src);
            pv[0][r] = mv[0][r] * __ldg(tb  + src);
            pv[1][r] = mv[1][r] * __ldg(tq  + src);
            pv[2][r] = mv[2][r] * __ldg(tn  + src);
            pv[3][r] = mv[3][r] * __ldg(tqx + src);
        }
#pragma unroll 4
        for (int b = 0; b < 16; b++) {
            float f0 = sf[b * 4 + 0], f1 = sf[b * 4 + 1];
            float f2 = sf[b * 4 + 2], f3 = sf[b * 4 + 3];
            uint4 u;
            u.x = to_tf32(wv[0] + f0 * pv[0][0] + f1 * pv[1][0] + f2 * pv[2][0] + f3 * pv[3][0]);
            u.y = to_tf32(wv[1] + f0 * pv[0][1] + f1 * pv[1][1] + f2 * pv[2][1] + f3 * pv[3][1]);
            u.z = to_tf32(wv[2] + f0 * pv[0][2] + f1 * pv[1][2] + f2 * pv[2][2] + f3 * pv[3][2]);
            u.w = to_tf32(wv[3] + f0 * pv[0][3] + f1 * pv[1][3] + f2 * pv[2][3] + f3 * pv[3][3]);
            size_t idx = (((((size_t)(b * 4 + cls) * 64 + kc) * 2 + kstep) * 8 + cotile) * 32
                          + lane) * 4;
            *(uint4*)(wout + idx) = u;
        }
    }
}

// ===========================================================================
// Kernel 2: tf32 mma.sync implicit-GEMM deconv.
// Per CTA: (b, cls, ntile): D[co=128, n=128] = sum_k A[k,co]*X[k,n], K=1024.
// 128 threads = 4 warps (2m x 2n), warp tile 64co x 64n.
// A: direct LDG.128 fragments from fragment-major g_wsyn (no smem),
//    register double-buffered per k8 step.
// B: smem double-buffered, chunk K=16, stride 136 (conflict-free frag LDS).
// ===========================================================================
#define SDB 136

__global__ __launch_bounds__(128, 2)
void deconv_mma(const float* __restrict__ x,
                const float* __restrict__ bias,
                const float* __restrict__ prelu_a,
                float* __restrict__ out)
{
    __shared__ uint32_t Bs[2][16 * SDB];

    const int tid  = threadIdx.x;
    const int wid  = tid >> 5;
    const int lane = tid & 31;
    const int g    = lane >> 2;
    const int t    = lane & 3;
    const int warp_m = wid >> 1;         // 0..1
    const int warp_n = wid & 1;          // 0..1
    const int cow = warp_m * 64;
    const int cnw = warp_n * 64;

    const int y0  = blockIdx.x * 2;      // two class-rows (128 n) per CTA
    const int cls = blockIdx.y;
    const int b   = blockIdx.z;
    const int py  = cls >> 1, px = cls & 1;
    const int sy  = py ? 1 : -1;
    const int sx  = px ? 1 : -1;

    // ---- B staging geometry: one thread per n column ----
    const int n  = tid;                  // 0..127
    const int ry = n >> 6, xx = n & 63;
    const int iy1 = y0 + ry + sy;
    const int ix1 = xx + sx;
    const bool oky = (unsigned)iy1 < (unsigned)H_IN;
    const bool okx = (unsigned)ix1 < (unsigned)W_IN;
    const int off0 = (y0 + ry) * W_IN + xx;
    const int dyo  = sy * W_IN;

    const float* __restrict__ xb = x + (size_t)b * (C_IN * H_IN * W_IN);
    // A fragment base (uint4 units): per (b,cls) slice is 32768 uint4.
    const uint4* __restrict__ pa =
        (const uint4*)g_wsyn + (size_t)(b * 4 + cls) * 32768 + warp_m * (4 * 32) + lane;

    float acc[4][8][4];
#pragma unroll
    for (int i = 0; i < 4; i++)
#pragma unroll
        for (int j = 0; j < 8; j++)
#pragma unroll
            for (int q = 0; q < 4; q++) acc[i][j][q] = 0.0f;

    float4 vb[4];
    uint4 afA[4], afB[4];

    auto ldA = [&](int kc, int kstep, uint4* af) {
        const uint4* p = pa + (size_t)(kc * 2 + kstep) * 256;
        af[0] = p[0];
        af[1] = p[32];
        af[2] = p[64];
        af[3] = p[96];
    };
    auto ldB = [&](int kc) {
#pragma unroll
        for (int c = 0; c < 4; c++) {
            const float* xc = xb + (size_t)(kc * 4 + c) * (H_IN * W_IN);
            float4 v;
            v.x = xc[off0];
            v.y = okx ? xc[off0 + sx] : 0.0f;
            v.z = oky ? xc[off0 + dyo] : 0.0f;
            v.w = (oky && okx) ? xc[off0 + dyo + sx] : 0.0f;
            vb[c] = v;
        }
    };
    auto stB = [&](int buf) {
        uint32_t* Bp = Bs[buf];
#pragma unroll
        for (int c = 0; c < 4; c++) {
            Bp[(c * 4 + 0) * SDB + n] = to_tf32(vb[c].x);
            Bp[(c * 4 + 1) * SDB + n] = to_tf32(vb[c].y);
            Bp[(c * 4 + 2) * SDB + n] = to_tf32(vb[c].z);
            Bp[(c * 4 + 3) * SDB + n] = to_tf32(vb[c].w);
        }
    };
    auto compute = [&](int buf, int ks, uint4* af) {
        const uint32_t* Bp = Bs[buf];
        uint32_t bf[8][2];
#pragma unroll
        for (int nt = 0; nt < 8; nt++) {
            int nn = cnw + nt * 8 + g;
            bf[nt][0] = Bp[(ks + t) * SDB + nn];
            bf[nt][1] = Bp[(ks + t + 4) * SDB + nn];
        }
#pragma unroll
        for (int mt = 0; mt < 4; mt++)
#pragma unroll
            for (int nt = 0; nt < 8; nt++)
                mma8(acc[mt][nt], af[mt].x, af[mt].y, af[mt].z, af[mt].w,
                     bf[nt][0], bf[nt][1]);
    };

    // ---- Mainloop: 64 chunks of K=16 ----
    ldB(0);
    stB(0);
    ldA(0, 0, afA);
    __syncthreads();
#pragma unroll 1
    for (int kc = 0; kc < 64; kc++) {
        const int buf = kc & 1;
        if (kc < 63) ldB(kc + 1);          // prefetch next chunk's X gathers
        ldA(kc, 1, afB);                    // prefetch kstep 1 fragments
        compute(buf, 0, afA);
        if (kc < 63) ldA(kc + 1, 0, afA);  // prefetch next chunk kstep 0
        compute(buf, 8, afB);
        if (kc < 63) {
            stB(buf ^ 1);
            __syncthreads();
        }
    }

    // ---- Epilogue: bias + PReLU, interleaved store ----
    const float pa_ = prelu_a[0];
#pragma unroll
    for (int mt = 0; mt < 4; mt++) {
        int c0r = cow + mt * 16 + g;
        float bv0 = __ldg(bias + c0r);
        float bv1 = __ldg(bias + c0r + 8);
#pragma unroll
        for (int rr = 0; rr < 2; rr++) {
            int co = c0r + rr * 8;
            float bi = rr ? bv1 : bv0;
            float* ob = out + (size_t)(b * C_OUT + co) * (H_OUT * W_OUT);
#pragma unroll
            for (int nt = 0; nt < 8; nt++) {
                int n0 = cnw + nt * 8 + t * 2;
                int ry2 = n0 >> 6, xx2 = n0 & 63;
                int oy = (y0 + ry2) * 2 + py;
                int ox = xx2 * 2 + px;
                float v0 = acc[mt][nt][rr * 2 + 0] + bi;
                float v1 = acc[mt][nt][rr * 2 + 1] + bi;
                v0 = (v0 >= 0.0f) ? v0 : pa_ * v0;
                v1 = (v1 >= 0.0f) ? v1 : pa_ * v1;
                ob[oy * W_OUT + ox]     = v0;
                ob[oy * W_OUT + ox + 2] = v1;
            }
        }
    }
}

// ===========================================================================
// Launch. Inputs: x, feature, weight, t_bayer, t_quad, t_nano, t_qxq,
// m_bayer, m_quad, m_nano, m_qxq, bias, prelu_a
// ===========================================================================
extern "C" void kernel_launch(void* const* d_in, const int* in_sizes, int n_in,
                              void* d_out, int out_size)
{
    const float* x       = (const float*)d_in[0];
    const float* feature = (const float*)d_in[1];
    const float* weight  = (const float*)d_in[2];
    const float* tb      = (const float*)d_in[3];
    const float* tq      = (const float*)d_in[4];
    const float* tn      = (const float*)d_in[5];
    const float* tqx     = (const float*)d_in[6];
    const float* mb      = (const float*)d_in[7];
    const float* mq      = (const float*)d_in[8];
    const float* mn      = (const float*)d_in[9];
    const float* mqx     = (const float*)d_in[10];
    const float* bias    = (const float*)d_in[11];
    const float* pa      = (const float*)d_in[12];
    float* out = (float*)d_out;

    // Kernel 1: fragment-major weight synthesis (each src element read once)
    synth_kernel<<<128, 256>>>(feature, weight, tb, tq, tn, tqx, mb, mq, mn, mqx);

    // Kernel 2: 32 n-tiles x 4 parity classes x 16 samples
    dim3 grid(32, 4, 16);
    deconv_mma<<<grid, 128>>>(x, bias, pa, out);
}